// round 6
// baseline (speedup 1.0000x reference)
#include <cuda_runtime.h>

#define T_LEN   16384
#define NUMB    64
#define KTAPS   129
#define TILE_T  128
#define BPB     8       // bands per block (1 per warp)
#define THREADS 256
#define NGROUPS (NUMB / BPB)

typedef unsigned long long ull;

// Packed-dup RBF params: per (b,c) 4 float4s:
//  [0] = {-sL, -sL, 2sLc, 2sLc} (real)   [1] = {-sLc^2, -sLc^2, fc, fc} (real)
//  [2],[3] same for imag side.
__device__ float4 g_P2[NUMB * NUMB * 4];
__device__ float  g_part[NGROUPS][T_LEN];   // per band-group partial (real only)

// ---- f32x2 helpers ----
#define FMA2(d, a, b, c) asm("fma.rn.f32x2 %0, %1, %2, %3;" : "=l"(d) : "l"(a), "l"(b), "l"(c))
#define MUL2(d, a, b)    asm("mul.rn.f32x2 %0, %1, %2;"     : "=l"(d) : "l"(a), "l"(b))
#define PACK2(d, lo, hi) asm("mov.b64 %0, {%1, %2};" : "=l"(d) : "f"(lo), "f"(hi))
#define UNPACK2(lo, hi, s) asm("mov.b64 {%0, %1}, %2;" : "=f"(lo), "=f"(hi) : "l"(s))

__device__ __forceinline__ float ex2f(float x) {
    float r; asm("ex2.approx.ftz.f32 %0, %1;" : "=f"(r) : "f"(x)); return r;
}
__device__ __forceinline__ float sqrtaf(float x) {
    float r; asm("sqrt.approx.f32 %0, %1;" : "=f"(r) : "f"(x)); return r;
}

__global__ void precompute_kernel(const float* __restrict__ cr, const float* __restrict__ ci,
                                  const float* __restrict__ sr, const float* __restrict__ si,
                                  const float* __restrict__ fr, const float* __restrict__ fi)
{
    int idx = blockIdx.x * blockDim.x + threadIdx.x;
    if (idx >= NUMB * NUMB) return;
    const float L = 1.4426950408889634f;  // log2(e)
    float s = sr[idx] * L;
    float c = cr[idx];
    g_P2[idx * 4 + 0] = make_float4(-s, -s, 2.0f * s * c, 2.0f * s * c);
    g_P2[idx * 4 + 1] = make_float4(-s * c * c, -s * c * c, fr[idx], fr[idx]);
    s = si[idx] * L;
    c = ci[idx];
    g_P2[idx * 4 + 2] = make_float4(-s, -s, 2.0f * s * c, 2.0f * s * c);
    g_P2[idx * 4 + 3] = make_float4(-s * c * c, -s * c * c, fi[idx], fi[idx]);
}

__global__ __launch_bounds__(THREADS)
void fused_kernel(const float* __restrict__ xr, const float* __restrict__ xi,
                  const float* __restrict__ w1r, const float* __restrict__ w1i,
                  const float* __restrict__ w3r, const float* __restrict__ w3i)
{
    __shared__ __align__(16) float sxr[TILE_T + 128];   // tile + 64 halo each side
    __shared__ __align__(16) float sxi[TILE_T + 128];
    __shared__ __align__(16) ull   swr2[BPB][130];      // (wr,wr) packed dup
    __shared__ __align__(16) ull   swi2[BPB][130];      // (wi,wi)
    __shared__ __align__(16) ull   snwi2[BPB][130];     // (-wi,-wi)
    __shared__ float sred[BPB][TILE_T];

    const int tid  = threadIdx.x;
    const int wb   = tid >> 5;        // local band (warp)
    const int lane = tid & 31;
    const int tileBase = blockIdx.x * TILE_T;
    const int band = blockIdx.y * BPB + wb;

    // ---- stage smem ----
    for (int i = tid; i < TILE_T + 128; i += THREADS) {
        int t = tileBase - 64 + i;
        bool ok = (t >= 0) && (t < T_LEN);
        sxr[i] = ok ? xr[t] : 0.0f;
        sxi[i] = ok ? xi[t] : 0.0f;
    }
    for (int i = tid; i < BPB * KTAPS; i += THREADS) {
        int bb = i / KTAPS, k = i - bb * KTAPS;
        int gb = blockIdx.y * BPB + bb;
        unsigned int ur  = __float_as_uint(w1r[gb * KTAPS + k]);
        unsigned int ui  = __float_as_uint(w1i[gb * KTAPS + k]);
        unsigned int uni = __float_as_uint(-w1i[gb * KTAPS + k]);
        swr2[bb][k]  = ((ull)ur  << 32) | ur;
        swi2[bb][k]  = ((ull)ui  << 32) | ui;
        snwi2[bb][k] = ((ull)uni << 32) | uni;
    }
    __syncthreads();

    // ---- complex conv, f32x2-packed (outputs j=0..3 as pairs 01 / 23) ----
    ull R01 = 0ull, R23 = 0ull, I01 = 0ull, I23 = 0ull;
    const float4* xr4 = (const float4*)sxr;
    const float4* xi4 = (const float4*)sxi;

    float4 Ar = xr4[lane];
    float4 Ai = xi4[lane];
    #pragma unroll
    for (int kg = 0; kg < 32; kg++) {
        float4 Br = xr4[lane + kg + 1];
        float4 Bi = xi4[lane + kg + 1];
        float axr[8] = {Ar.x, Ar.y, Ar.z, Ar.w, Br.x, Br.y, Br.z, Br.w};
        float axi[8] = {Ai.x, Ai.y, Ai.z, Ai.w, Bi.x, Bi.y, Bi.z, Bi.w};
        ull pXr[6], pXi[6];
        #pragma unroll
        for (int m = 0; m < 6; m++) {
            PACK2(pXr[m], axr[m], axr[m + 1]);
            PACK2(pXi[m], axi[m], axi[m + 1]);
        }
        #pragma unroll
        for (int kk = 0; kk < 4; kk++) {
            ull wr2  = swr2[wb][4 * kg + kk];
            ull wi2  = swi2[wb][4 * kg + kk];
            ull nwi2 = snwi2[wb][4 * kg + kk];
            FMA2(R01, pXr[kk],     wr2,  R01);
            FMA2(R01, pXi[kk],     nwi2, R01);
            FMA2(R23, pXr[kk + 2], wr2,  R23);
            FMA2(R23, pXi[kk + 2], nwi2, R23);
            FMA2(I01, pXr[kk],     wi2,  I01);
            FMA2(I01, pXi[kk],     wr2,  I01);
            FMA2(I23, pXr[kk + 2], wi2,  I23);
            FMA2(I23, pXi[kk + 2], wr2,  I23);
        }
        Ar = Br; Ai = Bi;
    }
    {   // tap k = 128
        float4 Cr = xr4[lane + 32];
        float4 Ci = xi4[lane + 32];
        ull p01r, p23r, p01i, p23i;
        PACK2(p01r, Cr.x, Cr.y); PACK2(p23r, Cr.z, Cr.w);
        PACK2(p01i, Ci.x, Ci.y); PACK2(p23i, Ci.z, Ci.w);
        ull wr2 = swr2[wb][128], wi2 = swi2[wb][128], nwi2 = snwi2[wb][128];
        FMA2(R01, p01r, wr2,  R01);
        FMA2(R01, p01i, nwi2, R01);
        FMA2(R23, p23r, wr2,  R23);
        FMA2(R23, p23i, nwi2, R23);
        FMA2(I01, p01r, wi2,  I01);
        FMA2(I01, p01i, wr2,  I01);
        FMA2(I23, p23r, wi2,  I23);
        FMA2(I23, p23i, wr2,  I23);
    }

    // ---- RBF mixture, packed: exp2(m*px + a*py + pz) ----
    ull m01, m23, a01, a23;
    MUL2(m01, R01, R01); FMA2(m01, I01, I01, m01);
    MUL2(m23, R23, R23); FMA2(m23, I23, I23, m23);
    {
        float f0, f1;
        UNPACK2(f0, f1, m01); PACK2(a01, sqrtaf(f0), sqrtaf(f1));
        UNPACK2(f0, f1, m23); PACK2(a23, sqrtaf(f0), sqrtaf(f1));
    }

    ull oR01 = 0ull, oR23 = 0ull, oI01 = 0ull, oI23 = 0ull;
    const ulonglong2* Pp = (const ulonglong2*)&g_P2[band * NUMB * 4];
    #pragma unroll 2
    for (int c = 0; c < NUMB; c++) {
        ulonglong2 P0 = Pp[c * 4 + 0];   // px2 (real), py2 (real)
        ulonglong2 P1 = Pp[c * 4 + 1];   // pz2 (real), pw2 (real)
        ulonglong2 P2 = Pp[c * 4 + 2];   // imag
        ulonglong2 P3 = Pp[c * 4 + 3];
        ull t01, t23, e01, e23;
        float f0, f1;
        // real side
        FMA2(t01, a01, P0.y, P1.x); FMA2(t01, m01, P0.x, t01);
        FMA2(t23, a23, P0.y, P1.x); FMA2(t23, m23, P0.x, t23);
        UNPACK2(f0, f1, t01); PACK2(e01, ex2f(f0), ex2f(f1));
        UNPACK2(f0, f1, t23); PACK2(e23, ex2f(f0), ex2f(f1));
        FMA2(oR01, e01, P1.y, oR01);
        FMA2(oR23, e23, P1.y, oR23);
        // imag side
        FMA2(t01, a01, P2.y, P3.x); FMA2(t01, m01, P2.x, t01);
        FMA2(t23, a23, P2.y, P3.x); FMA2(t23, m23, P2.x, t23);
        UNPACK2(f0, f1, t01); PACK2(e01, ex2f(f0), ex2f(f1));
        UNPACK2(f0, f1, t23); PACK2(e23, ex2f(f0), ex2f(f1));
        FMA2(oI01, e01, P3.y, oI01);
        FMA2(oI23, e23, P3.y, oI23);
    }

    // ---- combine + band weight (real output only) ----
    float x1r[4], x1i[4], oR[4], oI[4];
    UNPACK2(x1r[0], x1r[1], R01); UNPACK2(x1r[2], x1r[3], R23);
    UNPACK2(x1i[0], x1i[1], I01); UNPACK2(x1i[2], x1i[3], I23);
    UNPACK2(oR[0], oR[1], oR01);  UNPACK2(oR[2], oR[3], oR23);
    UNPACK2(oI[0], oI[1], oI01);  UNPACK2(oI[2], oI[3], oI23);

    float w3rb = __ldg(&w3r[band]);
    float w3ib = __ldg(&w3i[band]);
    #pragma unroll
    for (int j = 0; j < 4; j++) {
        float q   = oR[j] + 1.0f;
        float x2r = q * x1r[j] - oI[j] * x1i[j];
        float x2i = q * x1i[j] + oI[j] * x1r[j];
        sred[wb][4 * lane + j] = x2r * w3rb - x2i * w3ib;   // real part of y3
    }
    __syncthreads();

    // ---- reduce 8 bands within block, write partial for this band group ----
    if (tid < TILE_T) {
        float r = 0.f;
        #pragma unroll
        for (int w = 0; w < BPB; w++) r += sred[w][tid];
        g_part[blockIdx.y][tileBase + tid] = r;
    }
}

__global__ __launch_bounds__(256)
void reduce_kernel(float* __restrict__ out)
{
    int t = blockIdx.x * blockDim.x + threadIdx.x;
    if (t >= T_LEN) return;
    float r = 0.f;
    #pragma unroll
    for (int g = 0; g < NGROUPS; g++) r += g_part[g][t];
    out[t] = r;
}

extern "C" void kernel_launch(void* const* d_in, const int* in_sizes, int n_in,
                              void* d_out, int out_size)
{
    // Input ordering: order A (dict/signature) confirmed (in_sizes[0]==16384).
    int I_xr, I_xi, I_w1r, I_w1i, I_cr, I_ci, I_sr, I_si, I_fcr, I_fci, I_w3r, I_w3i;
    if (in_sizes[0] == T_LEN) {
        I_xr = 0;  I_xi = 1;  I_w1r = 2; I_w1i = 3; I_cr = 4;  I_ci = 5;
        I_sr = 6;  I_si = 7;  I_fcr = 8; I_fci = 9; I_w3r = 10; I_w3i = 11;
    } else {
        I_ci = 0;  I_cr = 1;  I_fci = 2; I_fcr = 3; I_si = 4;  I_sr = 5;
        I_w1i = 6; I_w1r = 7; I_w3i = 8; I_w3r = 9; I_xi = 10; I_xr = 11;
    }

    const float* x_r  = (const float*)d_in[I_xr];
    const float* x_i  = (const float*)d_in[I_xi];
    const float* w1_r = (const float*)d_in[I_w1r];
    const float* w1_i = (const float*)d_in[I_w1i];
    const float* c_r  = (const float*)d_in[I_cr];
    const float* c_i  = (const float*)d_in[I_ci];
    const float* s_r  = (const float*)d_in[I_sr];
    const float* s_i  = (const float*)d_in[I_si];
    const float* fc_r = (const float*)d_in[I_fcr];
    const float* fc_i = (const float*)d_in[I_fci];
    const float* w3_r = (const float*)d_in[I_w3r];
    const float* w3_i = (const float*)d_in[I_w3i];
    float* out = (float*)d_out;

    precompute_kernel<<<(NUMB * NUMB + 255) / 256, 256>>>(c_r, c_i, s_r, s_i, fc_r, fc_i);

    dim3 grid(T_LEN / TILE_T, NGROUPS);
    fused_kernel<<<grid, THREADS>>>(x_r, x_i, w1_r, w1_i, w3_r, w3_i);

    reduce_kernel<<<T_LEN / 256, 256>>>(out);
}

// round 7
// speedup vs baseline: 1.3935x; 1.3935x over previous
#include <cuda_runtime.h>

#define T_LEN   16384
#define NUMB    64
#define KTAPS   129
#define TILE_T  128
#define BPB     8       // bands per block (1 per warp)
#define THREADS 256
#define NGROUPS (NUMB / BPB)

__device__ float g_part[NGROUPS][T_LEN];   // per band-group partial (real only)

__device__ __forceinline__ float ex2f(float x) {
    float r; asm("ex2.approx.ftz.f32 %0, %1;" : "=f"(r) : "f"(x)); return r;
}
__device__ __forceinline__ float sqrtaf(float x) {
    float r; asm("sqrt.approx.f32 %0, %1;" : "=f"(r) : "f"(x)); return r;
}

__global__ __launch_bounds__(THREADS)
void fused_kernel(const float* __restrict__ xr, const float* __restrict__ xi,
                  const float* __restrict__ w1r, const float* __restrict__ w1i,
                  const float* __restrict__ cr,  const float* __restrict__ ci,
                  const float* __restrict__ sr,  const float* __restrict__ si,
                  const float* __restrict__ fr,  const float* __restrict__ fi,
                  const float* __restrict__ w3r, const float* __restrict__ w3i)
{
    __shared__ __align__(16) float  sxr[TILE_T + 128];      // tile + 64 halo each side
    __shared__ __align__(16) float  sxi[TILE_T + 128];
    __shared__ __align__(16) float2 swp[BPB][130];          // interleaved (wr,wi), padded
    __shared__ __align__(16) float4 sPr[BPB][NUMB];         // {-sL, 2sLc, -sLc^2, fc}
    __shared__ __align__(16) float4 sPi[BPB][NUMB];
    __shared__ float sred[BPB][TILE_T];

    const int tid  = threadIdx.x;
    const int wb   = tid >> 5;        // local band (warp)
    const int lane = tid & 31;
    const int tileBase = blockIdx.x * TILE_T;
    const int band = blockIdx.y * BPB + wb;

    // ---- stage smem ----
    for (int i = tid; i < TILE_T + 128; i += THREADS) {
        int t = tileBase - 64 + i;
        bool ok = (t >= 0) && (t < T_LEN);
        sxr[i] = ok ? xr[t] : 0.0f;
        sxi[i] = ok ? xi[t] : 0.0f;
    }
    for (int i = tid; i < BPB * KTAPS; i += THREADS) {
        int bb = i / KTAPS, k = i - bb * KTAPS;
        int gb = blockIdx.y * BPB + bb;
        swp[bb][k] = make_float2(w1r[gb * KTAPS + k], w1i[gb * KTAPS + k]);
    }
    // ---- inline RBF param precompute (L2-hot loads, trivial math) ----
    const float L = 1.4426950408889634f;  // log2(e)
    for (int i = tid; i < BPB * NUMB; i += THREADS) {
        int bb = i >> 6, c = i & 63;
        int idx = (blockIdx.y * BPB + bb) * NUMB + c;
        float s = __ldg(&sr[idx]) * L;
        float cc = __ldg(&cr[idx]);
        sPr[bb][c] = make_float4(-s, 2.0f * s * cc, -s * cc * cc, __ldg(&fr[idx]));
        s  = __ldg(&si[idx]) * L;
        cc = __ldg(&ci[idx]);
        sPi[bb][c] = make_float4(-s, 2.0f * s * cc, -s * cc * cc, __ldg(&fi[idx]));
    }
    __syncthreads();

    // ---- complex conv: 4 consecutive t per lane, sliding float4 window ----
    float x1r[4] = {0.f, 0.f, 0.f, 0.f};
    float x1i[4] = {0.f, 0.f, 0.f, 0.f};
    const float4* xr4 = (const float4*)sxr;
    const float4* xi4 = (const float4*)sxi;

    float4 Ar = xr4[lane];
    float4 Ai = xi4[lane];
    #pragma unroll
    for (int kg = 0; kg < 32; kg++) {
        float4 Br = xr4[lane + kg + 1];
        float4 Bi = xi4[lane + kg + 1];
        float4 wA = *(const float4*)&swp[wb][4 * kg];
        float4 wB = *(const float4*)&swp[wb][4 * kg + 2];
        float axr[8] = {Ar.x, Ar.y, Ar.z, Ar.w, Br.x, Br.y, Br.z, Br.w};
        float axi[8] = {Ai.x, Ai.y, Ai.z, Ai.w, Bi.x, Bi.y, Bi.z, Bi.w};
        float wr[4] = {wA.x, wA.z, wB.x, wB.z};
        float wi[4] = {wA.y, wA.w, wB.y, wB.w};
        #pragma unroll
        for (int kk = 0; kk < 4; kk++) {
            #pragma unroll
            for (int j = 0; j < 4; j++) {
                float xv = axr[kk + j], yv = axi[kk + j];
                x1r[j] = fmaf(xv,  wr[kk], x1r[j]);
                x1r[j] = fmaf(-yv, wi[kk], x1r[j]);
                x1i[j] = fmaf(xv,  wi[kk], x1i[j]);
                x1i[j] = fmaf(yv,  wr[kk], x1i[j]);
            }
        }
        Ar = Br; Ai = Bi;
    }
    {   // tap k = 128
        float4 Cr = xr4[lane + 32];
        float4 Ci = xi4[lane + 32];
        float2 wl = swp[wb][128];
        float cR[4] = {Cr.x, Cr.y, Cr.z, Cr.w};
        float cI[4] = {Ci.x, Ci.y, Ci.z, Ci.w};
        #pragma unroll
        for (int j = 0; j < 4; j++) {
            x1r[j] = fmaf(cR[j],  wl.x, x1r[j]);
            x1r[j] = fmaf(-cI[j], wl.y, x1r[j]);
            x1i[j] = fmaf(cR[j],  wl.y, x1i[j]);
            x1i[j] = fmaf(cI[j],  wl.x, x1i[j]);
        }
    }

    // ---- RBF mixture: exp2(m*px + a*py + pz) ----
    float m[4], a[4], oR[4] = {0.f,0.f,0.f,0.f}, oI[4] = {0.f,0.f,0.f,0.f};
    #pragma unroll
    for (int j = 0; j < 4; j++) {
        m[j] = x1r[j] * x1r[j] + x1i[j] * x1i[j];
        a[j] = sqrtaf(m[j]);
    }
    #pragma unroll 4
    for (int c = 0; c < NUMB; c++) {
        float4 pr = sPr[wb][c];
        float4 pi = sPi[wb][c];
        #pragma unroll
        for (int j = 0; j < 4; j++) {
            float er = ex2f(fmaf(m[j], pr.x, fmaf(a[j], pr.y, pr.z)));
            oR[j] = fmaf(er, pr.w, oR[j]);
            float ei = ex2f(fmaf(m[j], pi.x, fmaf(a[j], pi.y, pi.z)));
            oI[j] = fmaf(ei, pi.w, oI[j]);
        }
    }

    // ---- combine + band weight (real output only) ----
    float w3rb = __ldg(&w3r[band]);
    float w3ib = __ldg(&w3i[band]);
    #pragma unroll
    for (int j = 0; j < 4; j++) {
        float q   = oR[j] + 1.0f;
        float x2r = q * x1r[j] - oI[j] * x1i[j];
        float x2i = q * x1i[j] + oI[j] * x1r[j];
        sred[wb][4 * lane + j] = x2r * w3rb - x2i * w3ib;   // real part of y3
    }
    __syncthreads();

    // ---- reduce 8 bands within block, write partial for this band group ----
    if (tid < TILE_T) {
        float r = 0.f;
        #pragma unroll
        for (int w = 0; w < BPB; w++) r += sred[w][tid];
        g_part[blockIdx.y][tileBase + tid] = r;
    }
}

__global__ __launch_bounds__(256)
void reduce_kernel(float* __restrict__ out)
{
    int t = blockIdx.x * blockDim.x + threadIdx.x;
    if (t >= T_LEN) return;
    float r = 0.f;
    #pragma unroll
    for (int g = 0; g < NGROUPS; g++) r += g_part[g][t];
    out[t] = r;
}

extern "C" void kernel_launch(void* const* d_in, const int* in_sizes, int n_in,
                              void* d_out, int out_size)
{
    // Input ordering: order A (dict/signature) confirmed (in_sizes[0]==16384).
    int I_xr, I_xi, I_w1r, I_w1i, I_cr, I_ci, I_sr, I_si, I_fcr, I_fci, I_w3r, I_w3i;
    if (in_sizes[0] == T_LEN) {
        I_xr = 0;  I_xi = 1;  I_w1r = 2; I_w1i = 3; I_cr = 4;  I_ci = 5;
        I_sr = 6;  I_si = 7;  I_fcr = 8; I_fci = 9; I_w3r = 10; I_w3i = 11;
    } else {
        I_ci = 0;  I_cr = 1;  I_fci = 2; I_fcr = 3; I_si = 4;  I_sr = 5;
        I_w1i = 6; I_w1r = 7; I_w3i = 8; I_w3r = 9; I_xi = 10; I_xr = 11;
    }

    const float* x_r  = (const float*)d_in[I_xr];
    const float* x_i  = (const float*)d_in[I_xi];
    const float* w1_r = (const float*)d_in[I_w1r];
    const float* w1_i = (const float*)d_in[I_w1i];
    const float* c_r  = (const float*)d_in[I_cr];
    const float* c_i  = (const float*)d_in[I_ci];
    const float* s_r  = (const float*)d_in[I_sr];
    const float* s_i  = (const float*)d_in[I_si];
    const float* fc_r = (const float*)d_in[I_fcr];
    const float* fc_i = (const float*)d_in[I_fci];
    const float* w3_r = (const float*)d_in[I_w3r];
    const float* w3_i = (const float*)d_in[I_w3i];
    float* out = (float*)d_out;

    dim3 grid(T_LEN / TILE_T, NGROUPS);
    fused_kernel<<<grid, THREADS>>>(x_r, x_i, w1_r, w1_i,
                                    c_r, c_i, s_r, s_i, fc_r, fc_i,
                                    w3_r, w3_i);

    reduce_kernel<<<T_LEN / 256, 256>>>(out);
}

// round 8
// speedup vs baseline: 1.5000x; 1.0765x over previous
#include <cuda_runtime.h>

#define T_LEN   16384
#define NUMB    64
#define KTAPS   129
#define TILE_T  128
#define BPB     8       // bands per block (1 per warp)
#define THREADS 256
#define NGROUPS (NUMB / BPB)

// t-major partials: 8 floats (=32B, float4x2) per t, one slot per band group
__device__ float4 g_part[T_LEN][2];

__device__ __forceinline__ float ex2f(float x) {
    float r; asm("ex2.approx.ftz.f32 %0, %1;" : "=f"(r) : "f"(x)); return r;
}
__device__ __forceinline__ float sqrtaf(float x) {
    float r; asm("sqrt.approx.f32 %0, %1;" : "=f"(r) : "f"(x)); return r;
}

__global__ __launch_bounds__(THREADS)
void fused_kernel(const float* __restrict__ xr, const float* __restrict__ xi,
                  const float* __restrict__ w1r, const float* __restrict__ w1i,
                  const float* __restrict__ cr,  const float* __restrict__ ci,
                  const float* __restrict__ sr,  const float* __restrict__ si,
                  const float* __restrict__ fr,  const float* __restrict__ fi,
                  const float* __restrict__ w3r, const float* __restrict__ w3i)
{
    // conv x-arrays and sred never live simultaneously -> union (sync-guarded)
    __shared__ __align__(16) union {
        struct { float r[TILE_T + 128]; float i[TILE_T + 128]; float s[TILE_T + 128]; } cx;
        float sred[BPB][TILE_T];
    } u;
    __shared__ __align__(16) float swr[BPB][132];   // wr
    __shared__ __align__(16) float swd[BPB][132];   // wi - wr
    __shared__ __align__(16) float sws[BPB][132];   // wi + wr
    __shared__ __align__(16) float4 sPq[BPB][NUMB]; // {pxr, pyr, pxi, pyi}
    __shared__ __align__(16) float2 sPw[BPB][NUMB]; // {fc_r*2^pzr, fc_i*2^pzi}

    const int tid  = threadIdx.x;
    const int wb   = tid >> 5;        // local band (warp)
    const int lane = tid & 31;
    const int tileBase = blockIdx.x * TILE_T;
    const int band = blockIdx.y * BPB + wb;

    // ---- stage x tile + halo, with precomputed sum array ----
    for (int i = tid; i < TILE_T + 128; i += THREADS) {
        int t = tileBase - 64 + i;
        bool ok = (t >= 0) && (t < T_LEN);
        float vr = ok ? xr[t] : 0.0f;
        float vi = ok ? xi[t] : 0.0f;
        u.cx.r[i] = vr;
        u.cx.i[i] = vi;
        u.cx.s[i] = vr + vi;
    }
    // ---- stage Karatsuba weight triplets ----
    for (int i = tid; i < BPB * KTAPS; i += THREADS) {
        int bb = i / KTAPS, k = i - bb * KTAPS;
        int gb = blockIdx.y * BPB + bb;
        float wr = w1r[gb * KTAPS + k];
        float wi = w1i[gb * KTAPS + k];
        swr[bb][k] = wr;
        swd[bb][k] = wi - wr;
        sws[bb][k] = wi + wr;
    }
    // ---- inline RBF param precompute (2^pz folded into mixture weight) ----
    const float L = 1.4426950408889634f;  // log2(e)
    for (int i = tid; i < BPB * NUMB; i += THREADS) {
        int bb = i >> 6, c = i & 63;
        int idx = (blockIdx.y * BPB + bb) * NUMB + c;
        float s  = __ldg(&sr[idx]) * L;
        float cc = __ldg(&cr[idx]);
        float pxr = -s, pyr = 2.0f * s * cc;
        float pwr = __ldg(&fr[idx]) * ex2f(-s * cc * cc);
        s  = __ldg(&si[idx]) * L;
        cc = __ldg(&ci[idx]);
        float pxi = -s, pyi = 2.0f * s * cc;
        float pwi = __ldg(&fi[idx]) * ex2f(-s * cc * cc);
        sPq[bb][c] = make_float4(pxr, pyr, pxi, pyi);
        sPw[bb][c] = make_float2(pwr, pwi);
    }
    __syncthreads();

    // ---- Karatsuba complex conv: 3 FFMA/tap/output ----
    // A = sum wr*(xr+xi), B = sum xr*(wi-wr), C = sum xi*(wi+wr)
    // x1r = A - C, x1i = A + B
    float A[4] = {0.f,0.f,0.f,0.f}, B[4] = {0.f,0.f,0.f,0.f}, C[4] = {0.f,0.f,0.f,0.f};
    const float4* xs4 = (const float4*)u.cx.s;
    const float4* xr4 = (const float4*)u.cx.r;
    const float4* xi4 = (const float4*)u.cx.i;

    float4 As = xs4[lane], Ar = xr4[lane], Ai = xi4[lane];
    #pragma unroll
    for (int kg = 0; kg < 32; kg++) {
        float4 Bs = xs4[lane + kg + 1];
        float4 Br = xr4[lane + kg + 1];
        float4 Bi = xi4[lane + kg + 1];
        float4 wr4 = *(const float4*)&swr[wb][4 * kg];
        float4 wd4 = *(const float4*)&swd[wb][4 * kg];
        float4 ws4 = *(const float4*)&sws[wb][4 * kg];
        float axs[8] = {As.x, As.y, As.z, As.w, Bs.x, Bs.y, Bs.z, Bs.w};
        float axr[8] = {Ar.x, Ar.y, Ar.z, Ar.w, Br.x, Br.y, Br.z, Br.w};
        float axi[8] = {Ai.x, Ai.y, Ai.z, Ai.w, Bi.x, Bi.y, Bi.z, Bi.w};
        float wrv[4] = {wr4.x, wr4.y, wr4.z, wr4.w};
        float wdv[4] = {wd4.x, wd4.y, wd4.z, wd4.w};
        float wsv[4] = {ws4.x, ws4.y, ws4.z, ws4.w};
        #pragma unroll
        for (int kk = 0; kk < 4; kk++) {
            #pragma unroll
            for (int j = 0; j < 4; j++) {
                A[j] = fmaf(axs[kk + j], wrv[kk], A[j]);
                B[j] = fmaf(axr[kk + j], wdv[kk], B[j]);
                C[j] = fmaf(axi[kk + j], wsv[kk], C[j]);
            }
        }
        As = Bs; Ar = Br; Ai = Bi;
    }
    {   // tail tap k = 128: window float4 already in As/Ar/Ai (= index lane+32)
        float wr = swr[wb][128], wd = swd[wb][128], ws = sws[wb][128];
        float ts[4] = {As.x, As.y, As.z, As.w};
        float tr[4] = {Ar.x, Ar.y, Ar.z, Ar.w};
        float ti[4] = {Ai.x, Ai.y, Ai.z, Ai.w};
        #pragma unroll
        for (int j = 0; j < 4; j++) {
            A[j] = fmaf(ts[j], wr, A[j]);
            B[j] = fmaf(tr[j], wd, B[j]);
            C[j] = fmaf(ti[j], ws, C[j]);
        }
    }
    float x1r[4], x1i[4];
    #pragma unroll
    for (int j = 0; j < 4; j++) {
        x1r[j] = A[j] - C[j];
        x1i[j] = A[j] + B[j];
    }

    // ---- RBF mixture: exp2(m*px + a*py) * pw' ----
    float m[4], a[4], oR[4] = {0.f,0.f,0.f,0.f}, oI[4] = {0.f,0.f,0.f,0.f};
    #pragma unroll
    for (int j = 0; j < 4; j++) {
        m[j] = x1r[j] * x1r[j] + x1i[j] * x1i[j];
        a[j] = sqrtaf(m[j]);
    }
    #pragma unroll 4
    for (int c = 0; c < NUMB; c++) {
        float4 q = sPq[wb][c];
        float2 w = sPw[wb][c];
        #pragma unroll
        for (int j = 0; j < 4; j++) {
            float er = ex2f(fmaf(m[j], q.x, a[j] * q.y));
            oR[j] = fmaf(er, w.x, oR[j]);
            float ei = ex2f(fmaf(m[j], q.z, a[j] * q.w));
            oI[j] = fmaf(ei, w.y, oI[j]);
        }
    }

    // ---- combine + band weight (real output only) ----
    float w3rb = __ldg(&w3r[band]);
    float w3ib = __ldg(&w3i[band]);
    float yv[4];
    #pragma unroll
    for (int j = 0; j < 4; j++) {
        float q   = oR[j] + 1.0f;
        float x2r = q * x1r[j] - oI[j] * x1i[j];
        float x2i = q * x1i[j] + oI[j] * x1r[j];
        yv[j] = x2r * w3rb - x2i * w3ib;   // real part of y3
    }
    __syncthreads();   // all warps done reading u.cx before overlay reuse
    #pragma unroll
    for (int j = 0; j < 4; j++)
        u.sred[wb][4 * lane + j] = yv[j];
    __syncthreads();

    // ---- reduce 8 bands within block; t-major partial for fast final reduce ----
    if (tid < TILE_T) {
        float r = 0.f;
        #pragma unroll
        for (int w = 0; w < BPB; w++) r += u.sred[w][tid];
        ((float*)&g_part[tileBase + tid][0])[blockIdx.y] = r;
    }
}

__global__ __launch_bounds__(256)
void reduce_kernel(float* __restrict__ out)
{
    int t = blockIdx.x * blockDim.x + threadIdx.x;
    if (t >= T_LEN) return;
    float4 a = g_part[t][0];
    float4 b = g_part[t][1];
    out[t] = ((a.x + a.y) + (a.z + a.w)) + ((b.x + b.y) + (b.z + b.w));
}

extern "C" void kernel_launch(void* const* d_in, const int* in_sizes, int n_in,
                              void* d_out, int out_size)
{
    // Input ordering: order A (dict/signature) confirmed (in_sizes[0]==16384).
    int I_xr, I_xi, I_w1r, I_w1i, I_cr, I_ci, I_sr, I_si, I_fcr, I_fci, I_w3r, I_w3i;
    if (in_sizes[0] == T_LEN) {
        I_xr = 0;  I_xi = 1;  I_w1r = 2; I_w1i = 3; I_cr = 4;  I_ci = 5;
        I_sr = 6;  I_si = 7;  I_fcr = 8; I_fci = 9; I_w3r = 10; I_w3i = 11;
    } else {
        I_ci = 0;  I_cr = 1;  I_fci = 2; I_fcr = 3; I_si = 4;  I_sr = 5;
        I_w1i = 6; I_w1r = 7; I_w3i = 8; I_w3r = 9; I_xi = 10; I_xr = 11;
    }

    const float* x_r  = (const float*)d_in[I_xr];
    const float* x_i  = (const float*)d_in[I_xi];
    const float* w1_r = (const float*)d_in[I_w1r];
    const float* w1_i = (const float*)d_in[I_w1i];
    const float* c_r  = (const float*)d_in[I_cr];
    const float* c_i  = (const float*)d_in[I_ci];
    const float* s_r  = (const float*)d_in[I_sr];
    const float* s_i  = (const float*)d_in[I_si];
    const float* fc_r = (const float*)d_in[I_fcr];
    const float* fc_i = (const float*)d_in[I_fci];
    const float* w3_r = (const float*)d_in[I_w3r];
    const float* w3_i = (const float*)d_in[I_w3i];
    float* out = (float*)d_out;

    dim3 grid(T_LEN / TILE_T, NGROUPS);
    fused_kernel<<<grid, THREADS>>>(x_r, x_i, w1_r, w1_i,
                                    c_r, c_i, s_r, s_i, fc_r, fc_i,
                                    w3_r, w3_i);

    reduce_kernel<<<T_LEN / 256, 256>>>(out);
}

// round 9
// speedup vs baseline: 1.5475x; 1.0317x over previous
#include <cuda_runtime.h>

#define T_LEN   16384
#define NUMB    64
#define KTAPS   129
#define TILE_T  128
#define BPB     8       // bands per block (1 per warp)
#define THREADS 256
#define NGROUPS (NUMB / BPB)
#define NTILES  (T_LEN / TILE_T)

// t-major partials: 8 floats (=2x float4) per t, one slot per band group
__device__ float4 g_part[T_LEN][2];
// per-tile arrival tickets; zero-init at load, reset to 0 by last block each
// launch -> deterministic across graph replays
__device__ int g_cnt[NTILES];

__device__ __forceinline__ float ex2f(float x) {
    float r; asm("ex2.approx.ftz.f32 %0, %1;" : "=f"(r) : "f"(x)); return r;
}
__device__ __forceinline__ float sqrtaf(float x) {
    float r; asm("sqrt.approx.f32 %0, %1;" : "=f"(r) : "f"(x)); return r;
}

__global__ __launch_bounds__(THREADS)
void fused_kernel(const float* __restrict__ xr, const float* __restrict__ xi,
                  const float* __restrict__ w1r, const float* __restrict__ w1i,
                  const float* __restrict__ cr,  const float* __restrict__ ci,
                  const float* __restrict__ sr,  const float* __restrict__ si,
                  const float* __restrict__ fr,  const float* __restrict__ fi,
                  const float* __restrict__ w3r, const float* __restrict__ w3i,
                  float* __restrict__ out)
{
    // conv x-arrays and sred never live simultaneously -> union (sync-guarded)
    __shared__ __align__(16) union {
        struct { float r[TILE_T + 128]; float i[TILE_T + 128]; float s[TILE_T + 128]; } cx;
        float sred[BPB][TILE_T];
    } u;
    __shared__ __align__(16) float swr[BPB][132];   // wr
    __shared__ __align__(16) float swd[BPB][132];   // wi - wr
    __shared__ __align__(16) float sws[BPB][132];   // wi + wr
    __shared__ __align__(16) float4 sPq[BPB][NUMB]; // {pxr, pyr, pxi, pyi}
    __shared__ __align__(16) float2 sPw[BPB][NUMB]; // {fc_r*2^pzr, fc_i*2^pzi}
    __shared__ int s_ticket;

    const int tid  = threadIdx.x;
    const int wb   = tid >> 5;        // local band (warp)
    const int lane = tid & 31;
    const int tile = blockIdx.x;
    const int tileBase = tile * TILE_T;
    const int band = blockIdx.y * BPB + wb;

    // ---- stage x tile + halo, with precomputed sum array ----
    for (int i = tid; i < TILE_T + 128; i += THREADS) {
        int t = tileBase - 64 + i;
        bool ok = (t >= 0) && (t < T_LEN);
        float vr = ok ? xr[t] : 0.0f;
        float vi = ok ? xi[t] : 0.0f;
        u.cx.r[i] = vr;
        u.cx.i[i] = vi;
        u.cx.s[i] = vr + vi;
    }
    // ---- stage Karatsuba weight triplets ----
    for (int i = tid; i < BPB * KTAPS; i += THREADS) {
        int bb = i / KTAPS, k = i - bb * KTAPS;
        int gb = blockIdx.y * BPB + bb;
        float wr = w1r[gb * KTAPS + k];
        float wi = w1i[gb * KTAPS + k];
        swr[bb][k] = wr;
        swd[bb][k] = wi - wr;
        sws[bb][k] = wi + wr;
    }
    // ---- inline RBF param precompute (2^pz folded into mixture weight) ----
    const float L = 1.4426950408889634f;  // log2(e)
    for (int i = tid; i < BPB * NUMB; i += THREADS) {
        int bb = i >> 6, c = i & 63;
        int idx = (blockIdx.y * BPB + bb) * NUMB + c;
        float s  = __ldg(&sr[idx]) * L;
        float cc = __ldg(&cr[idx]);
        float pxr = -s, pyr = 2.0f * s * cc;
        float pwr = __ldg(&fr[idx]) * ex2f(-s * cc * cc);
        s  = __ldg(&si[idx]) * L;
        cc = __ldg(&ci[idx]);
        float pxi = -s, pyi = 2.0f * s * cc;
        float pwi = __ldg(&fi[idx]) * ex2f(-s * cc * cc);
        sPq[bb][c] = make_float4(pxr, pyr, pxi, pyi);
        sPw[bb][c] = make_float2(pwr, pwi);
    }
    __syncthreads();

    // ---- Karatsuba complex conv: 3 FFMA/tap/output ----
    // A = sum wr*(xr+xi), B = sum xr*(wi-wr), C = sum xi*(wi+wr)
    // x1r = A - C, x1i = A + B
    float A[4] = {0.f,0.f,0.f,0.f}, B[4] = {0.f,0.f,0.f,0.f}, C[4] = {0.f,0.f,0.f,0.f};
    const float4* xs4 = (const float4*)u.cx.s;
    const float4* xr4 = (const float4*)u.cx.r;
    const float4* xi4 = (const float4*)u.cx.i;

    float4 As = xs4[lane], Ar = xr4[lane], Ai = xi4[lane];
    #pragma unroll
    for (int kg = 0; kg < 32; kg++) {
        float4 Bs = xs4[lane + kg + 1];
        float4 Br = xr4[lane + kg + 1];
        float4 Bi = xi4[lane + kg + 1];
        float4 wr4 = *(const float4*)&swr[wb][4 * kg];
        float4 wd4 = *(const float4*)&swd[wb][4 * kg];
        float4 ws4 = *(const float4*)&sws[wb][4 * kg];
        float axs[8] = {As.x, As.y, As.z, As.w, Bs.x, Bs.y, Bs.z, Bs.w};
        float axr[8] = {Ar.x, Ar.y, Ar.z, Ar.w, Br.x, Br.y, Br.z, Br.w};
        float axi[8] = {Ai.x, Ai.y, Ai.z, Ai.w, Bi.x, Bi.y, Bi.z, Bi.w};
        float wrv[4] = {wr4.x, wr4.y, wr4.z, wr4.w};
        float wdv[4] = {wd4.x, wd4.y, wd4.z, wd4.w};
        float wsv[4] = {ws4.x, ws4.y, ws4.z, ws4.w};
        #pragma unroll
        for (int kk = 0; kk < 4; kk++) {
            #pragma unroll
            for (int j = 0; j < 4; j++) {
                A[j] = fmaf(axs[kk + j], wrv[kk], A[j]);
                B[j] = fmaf(axr[kk + j], wdv[kk], B[j]);
                C[j] = fmaf(axi[kk + j], wsv[kk], C[j]);
            }
        }
        As = Bs; Ar = Br; Ai = Bi;
    }
    {   // tail tap k = 128: window float4 already in As/Ar/Ai (= index lane+32)
        float wr = swr[wb][128], wd = swd[wb][128], ws = sws[wb][128];
        float ts[4] = {As.x, As.y, As.z, As.w};
        float tr[4] = {Ar.x, Ar.y, Ar.z, Ar.w};
        float ti[4] = {Ai.x, Ai.y, Ai.z, Ai.w};
        #pragma unroll
        for (int j = 0; j < 4; j++) {
            A[j] = fmaf(ts[j], wr, A[j]);
            B[j] = fmaf(tr[j], wd, B[j]);
            C[j] = fmaf(ti[j], ws, C[j]);
        }
    }
    float x1r[4], x1i[4];
    #pragma unroll
    for (int j = 0; j < 4; j++) {
        x1r[j] = A[j] - C[j];
        x1i[j] = A[j] + B[j];
    }

    // ---- RBF mixture: exp2(m*px + a*py) * pw' ----
    float m[4], a[4], oR[4] = {0.f,0.f,0.f,0.f}, oI[4] = {0.f,0.f,0.f,0.f};
    #pragma unroll
    for (int j = 0; j < 4; j++) {
        m[j] = x1r[j] * x1r[j] + x1i[j] * x1i[j];
        a[j] = sqrtaf(m[j]);
    }
    #pragma unroll 4
    for (int c = 0; c < NUMB; c++) {
        float4 q = sPq[wb][c];
        float2 w = sPw[wb][c];
        #pragma unroll
        for (int j = 0; j < 4; j++) {
            float er = ex2f(fmaf(m[j], q.x, a[j] * q.y));
            oR[j] = fmaf(er, w.x, oR[j]);
            float ei = ex2f(fmaf(m[j], q.z, a[j] * q.w));
            oI[j] = fmaf(ei, w.y, oI[j]);
        }
    }

    // ---- combine + band weight (real output only) ----
    float w3rb = __ldg(&w3r[band]);
    float w3ib = __ldg(&w3i[band]);
    float yv[4];
    #pragma unroll
    for (int j = 0; j < 4; j++) {
        float q   = oR[j] + 1.0f;
        float x2r = q * x1r[j] - oI[j] * x1i[j];
        float x2i = q * x1i[j] + oI[j] * x1r[j];
        yv[j] = x2r * w3rb - x2i * w3ib;   // real part of y3
    }
    __syncthreads();   // all warps done reading u.cx before overlay reuse
    #pragma unroll
    for (int j = 0; j < 4; j++)
        u.sred[wb][4 * lane + j] = yv[j];
    __syncthreads();

    // ---- reduce 8 bands within block; publish t-major partial ----
    if (tid < TILE_T) {
        float r = 0.f;
        #pragma unroll
        for (int w = 0; w < BPB; w++) r += u.sred[w][tid];
        ((float*)&g_part[tileBase + tid][0])[blockIdx.y] = r;
    }

    // ---- fence + ticket: last block of this tile finalizes ----
    __threadfence();
    if (tid == 0)
        s_ticket = atomicAdd(&g_cnt[tile], 1);
    __syncthreads();
    if (s_ticket == NGROUPS - 1) {
        if (tid < TILE_T) {
            int t = tileBase + tid;
            float4 pa = g_part[t][0];
            float4 pb = g_part[t][1];
            out[t] = ((pa.x + pa.y) + (pa.z + pa.w)) + ((pb.x + pb.y) + (pb.z + pb.w));
        }
        if (tid == 0)
            g_cnt[tile] = 0;   // reset for next launch / graph replay
    }
}

extern "C" void kernel_launch(void* const* d_in, const int* in_sizes, int n_in,
                              void* d_out, int out_size)
{
    // Input ordering: order A (dict/signature) confirmed (in_sizes[0]==16384).
    int I_xr, I_xi, I_w1r, I_w1i, I_cr, I_ci, I_sr, I_si, I_fcr, I_fci, I_w3r, I_w3i;
    if (in_sizes[0] == T_LEN) {
        I_xr = 0;  I_xi = 1;  I_w1r = 2; I_w1i = 3; I_cr = 4;  I_ci = 5;
        I_sr = 6;  I_si = 7;  I_fcr = 8; I_fci = 9; I_w3r = 10; I_w3i = 11;
    } else {
        I_ci = 0;  I_cr = 1;  I_fci = 2; I_fcr = 3; I_si = 4;  I_sr = 5;
        I_w1i = 6; I_w1r = 7; I_w3i = 8; I_w3r = 9; I_xi = 10; I_xr = 11;
    }

    const float* x_r  = (const float*)d_in[I_xr];
    const float* x_i  = (const float*)d_in[I_xi];
    const float* w1_r = (const float*)d_in[I_w1r];
    const float* w1_i = (const float*)d_in[I_w1i];
    const float* c_r  = (const float*)d_in[I_cr];
    const float* c_i  = (const float*)d_in[I_ci];
    const float* s_r  = (const float*)d_in[I_sr];
    const float* s_i  = (const float*)d_in[I_si];
    const float* fc_r = (const float*)d_in[I_fcr];
    const float* fc_i = (const float*)d_in[I_fci];
    const float* w3_r = (const float*)d_in[I_w3r];
    const float* w3_i = (const float*)d_in[I_w3i];
    float* out = (float*)d_out;

    dim3 grid(NTILES, NGROUPS);
    fused_kernel<<<grid, THREADS>>>(x_r, x_i, w1_r, w1_i,
                                    c_r, c_i, s_r, s_i, fc_r, fc_i,
                                    w3_r, w3_i, out);
}